// round 16
// baseline (speedup 1.0000x reference)
#include <cuda_runtime.h>
#include <cuda_fp16.h>
#include <cstdint>
#include <math.h>

// ---------------------------------------------------------------------------
// B=4, Q=K=4096, D=IN=256.
// R15 = R13 (sorted + split-KV flash, 295.8us) with scheduling/packing fixes:
//  - flash grid flattened 1D: batch fastest, (qt desc, split) next -> longest
//    CTAs of ALL batches and BOTH splits issue in wave 1 (R13 issued all of
//    split 0 before split 1, putting long split-1 CTAs on the critical path).
//  - QKV projections fused into one launch (grid.z selects operands).
//  - all 7 fp32->fp16 conversions in one launch.
//  - combine skips the split-1 partial read for sentinel rows (l1 == 0).
// ---------------------------------------------------------------------------

#define SPLIT 2

__device__ __half g_xq[4u * 4096u * 256u];
__device__ __half g_xk[4u * 4096u * 256u];
__device__ __half g_xv[4u * 4096u * 256u];
__device__ __half g_wq[65536], g_wk[65536], g_wv[65536], g_wo[65536];
__device__ __half g_qh[4u * 4096u * 256u];
__device__ __half g_kh[4u * 4096u * 256u];
__device__ __half g_vh[4u * 4096u * 256u];
__device__ __half g_vth[4u * 4096u * 256u];
__device__ __half g_atth[4u * 4096u * 256u];
__device__ int g_start[4 * 4096];
__device__ int g_perm[4 * 4096];
__device__ float g_pO[(size_t)SPLIT * 4u * 4096u * 256u];
__device__ float g_pM[SPLIT * 16384];
__device__ float g_pL[SPLIT * 16384];

// ======================= helpers =======================
__device__ __forceinline__ uint32_t smem_u32(const void* p) {
  uint32_t a;
  asm("{ .reg .u64 t; cvta.to.shared.u64 t, %1; cvt.u32.u64 %0, t; }"
      : "=r"(a) : "l"(p));
  return a;
}
__device__ __forceinline__ void cp16(uint32_t s, const void* g) {
  asm volatile("cp.async.cg.shared.global [%0], [%1], 16;\n" ::"r"(s), "l"(g));
}
__device__ __forceinline__ void cp_commit() {
  asm volatile("cp.async.commit_group;\n" ::: "memory");
}
template <int N>
__device__ __forceinline__ void cp_wait() {
  asm volatile("cp.async.wait_group %0;\n" ::"n"(N) : "memory");
}
__device__ __forceinline__ void mma16(float* d, const uint32_t* a, const uint32_t* b) {
  asm volatile(
      "mma.sync.aligned.m16n8k16.row.col.f32.f16.f16.f32 "
      "{%0,%1,%2,%3}, {%4,%5,%6,%7}, {%8,%9}, {%0,%1,%2,%3};"
      : "+f"(d[0]), "+f"(d[1]), "+f"(d[2]), "+f"(d[3])
      : "r"(a[0]), "r"(a[1]), "r"(a[2]), "r"(a[3]), "r"(b[0]), "r"(b[1]));
}
__device__ __forceinline__ uint32_t pack_half2(float a, float b) {
  __half2 h = __floats2half2_rn(a, b);
  return *(uint32_t*)&h;
}
__device__ __forceinline__ void store2(float* p, float d0, float d1) {
  float2 v; v.x = d0; v.y = d1;
  *(float2*)p = v;
}
__device__ __forceinline__ void store2(__half* p, float d0, float d1) {
  *(__half2*)p = __floats2half2_rn(d0, d1);
}

// ---------------------------------------------------------------------------
// Counting sort of queries by mask length (per batch). Ascending.
// ---------------------------------------------------------------------------
__global__ __launch_bounds__(1024) void sort_hist_scan(
    const int* __restrict__ mask, int* __restrict__ start) {
  __shared__ int hist[4096];
  __shared__ int sums[1024];
  __shared__ int sums2[1024];
  const int z = blockIdx.x;
  const int t = threadIdx.x;
#pragma unroll
  for (int i = 0; i < 4; i++) hist[t + i * 1024] = 0;
  __syncthreads();
#pragma unroll
  for (int i = 0; i < 4; i++)
    atomicAdd(&hist[mask[z * 4096 + t + i * 1024] - 1], 1);
  __syncthreads();
  const int c0 = hist[4 * t], c1 = hist[4 * t + 1];
  const int c2 = hist[4 * t + 2], c3 = hist[4 * t + 3];
  sums[t] = c0 + c1 + c2 + c3;
  __syncthreads();
  int* src = sums;
  int* dst = sums2;
  for (int off = 1; off < 1024; off <<= 1) {
    int v = src[t];
    if (t >= off) v += src[t - off];
    dst[t] = v;
    __syncthreads();
    int* tmp = src; src = dst; dst = tmp;
  }
  const int excl = (t == 0) ? 0 : src[t - 1];
  start[z * 4096 + 4 * t] = excl;
  start[z * 4096 + 4 * t + 1] = excl + c0;
  start[z * 4096 + 4 * t + 2] = excl + c0 + c1;
  start[z * 4096 + 4 * t + 3] = excl + c0 + c1 + c2;
}

__global__ __launch_bounds__(256) void sort_scatter(
    const int* __restrict__ mask, int* __restrict__ start,
    int* __restrict__ perm) {
  const int z = blockIdx.y;
  const int i = blockIdx.x * 256 + threadIdx.x;
  const int len = mask[z * 4096 + i];
  const int pos = atomicAdd(&start[z * 4096 + len - 1], 1);
  perm[z * 4096 + pos] = i;
}

// ---------------------------------------------------------------------------
// fp16 GEMM core (proven): C[16384,256] = A[16384,256] @ B[256,256]^T + bias
// CTA 128x128, BK=32, 8 warps (2m x 4n), double-buffered cp.async.
// ---------------------------------------------------------------------------
#define S32 20
#define TILE_WORDS (128 * S32)
#define STAGE_BYTES (2 * TILE_WORDS * 4)
#define GEMM_SMEM (2 * STAGE_BYTES)

template <typename OutT>
__device__ __forceinline__ void gemm_core(
    const __half* __restrict__ A, const __half* __restrict__ B,
    const float* __restrict__ bias, OutT* __restrict__ C,
    int bm, int bn, char* dyn_smem) {
  const uint32_t smem_base = smem_u32(dyn_smem);
  const int tid = threadIdx.x;
  const int lane = tid & 31;
  const int wid = tid >> 5;
  const int wm = wid & 1;
  const int wn = wid >> 1;

  const __half* gA = A + (size_t)bm * 256;
  const __half* gB = B + (size_t)bn * 256;

  float acc[4][4][4];
#pragma unroll
  for (int i = 0; i < 4; i++)
#pragma unroll
    for (int j = 0; j < 4; j++)
#pragma unroll
      for (int p = 0; p < 4; p++) acc[i][j][p] = 0.0f;

  const int ldRow = tid & 127;
  const bool isB = tid >= 128;
  const __half* gRowBase = (isB ? gB : gA);
  const uint32_t sRowOff = (isB ? STAGE_BYTES / 2 : 0) + ldRow * (S32 * 4);

  auto load_tiles = [&](int stage, int k0) {
    const uint32_t s0 = smem_base + stage * STAGE_BYTES + sRowOff;
    const __half* g0 = gRowBase + (size_t)ldRow * 256 + k0;
#pragma unroll
    for (int ch = 0; ch < 4; ch++) cp16(s0 + ch * 16, g0 + ch * 8);
    cp_commit();
  };

  const int g = lane >> 2;
  const int c = lane & 3;

  const int KT = 8;  // 256 / 32
  load_tiles(0, 0);
  for (int it = 0; it < KT; ++it) {
    const int buf = it & 1;
    if (it + 1 < KT) {
      load_tiles(buf ^ 1, (it + 1) << 5);
      cp_wait<1>();
    } else {
      cp_wait<0>();
    }
    __syncthreads();

    const uint32_t* As32 = (const uint32_t*)(dyn_smem + buf * STAGE_BYTES);
    const uint32_t* Bs32 = As32 + TILE_WORDS;

#pragma unroll
    for (int kk = 0; kk < 2; ++kk) {
      const int ko = kk * 8;
      uint32_t af[4][4], bf[4][2];
#pragma unroll
      for (int mt = 0; mt < 4; mt++) {
        const int base = (wm * 64 + mt * 16 + g) * S32 + c + ko;
        af[mt][0] = As32[base];
        af[mt][1] = As32[base + 8 * S32];
        af[mt][2] = As32[base + 4];
        af[mt][3] = As32[base + 8 * S32 + 4];
      }
#pragma unroll
      for (int nt = 0; nt < 4; nt++) {
        const int base = (wn * 32 + nt * 8 + g) * S32 + c + ko;
        bf[nt][0] = Bs32[base];
        bf[nt][1] = Bs32[base + 4];
      }
#pragma unroll
      for (int mt = 0; mt < 4; mt++)
#pragma unroll
        for (int nt = 0; nt < 4; nt++) mma16(acc[mt][nt], af[mt], bf[nt]);
    }
    __syncthreads();
  }

  const int c2 = c * 2;
#pragma unroll
  for (int mt = 0; mt < 4; mt++) {
    const int row0 = bm + wm * 64 + mt * 16 + g;
#pragma unroll
    for (int nt = 0; nt < 4; nt++) {
      const int col = bn + wn * 32 + nt * 8 + c2;
      float d0 = acc[mt][nt][0] + bias[col];
      float d1 = acc[mt][nt][1] + bias[col + 1];
      float d2 = acc[mt][nt][2] + bias[col];
      d2 = acc[mt][nt][2] + bias[col];
      float d3 = acc[mt][nt][3] + bias[col + 1];
      store2(C + (size_t)row0 * 256 + col, d0, d1);
      store2(C + (size_t)(row0 + 8) * 256 + col, d2, d3);
    }
  }
}

// Fused QKV projections: grid (2, 128, 3); z selects operand set.
__global__ void __launch_bounds__(256, 2) hgemm_qkv(
    const __half* xq, const __half* wq, const float* bq, __half* qh,
    const __half* xk, const __half* wk, const float* bk, __half* kh,
    const __half* xv, const __half* wv, const float* bv, __half* vh) {
  extern __shared__ char dyn_smem[];
  const __half* A;
  const __half* B;
  const float* bias;
  __half* C;
  if (blockIdx.z == 0) { A = xq; B = wq; bias = bq; C = qh; }
  else if (blockIdx.z == 1) { A = xk; B = wk; bias = bk; C = kh; }
  else { A = xv; B = wv; bias = bv; C = vh; }
  gemm_core<__half>(A, B, bias, C, blockIdx.y * 128, blockIdx.x * 128, dyn_smem);
}

// Output projection: grid (2, 128, 1)
__global__ void __launch_bounds__(256, 2) hgemm_out(
    const __half* atth, const __half* wo, const float* bo, float* out) {
  extern __shared__ char dyn_smem[];
  gemm_core<float>(atth, wo, bo, out, blockIdx.y * 128, blockIdx.x * 128, dyn_smem);
}

// ---------------------------------------------------------------------------
// Split-KV flash attention, 1D grid (256): batch fastest, (qt desc, split)
// next -> longest CTAs of all batches/splits issue first.
// ---------------------------------------------------------------------------
#define OFF_Q 0
#define OFF_K0 (128 * 528)
#define OFF_K1 (OFF_K0 + 64 * 528)
#define OFF_V0 (OFF_K1 + 64 * 528)
#define OFF_V1 (OFF_V0 + 256 * 144)
#define FLASH_SMEM (OFF_V1 + 256 * 144)

__global__ void __launch_bounds__(256, 1) flash_attn(
    const __half* __restrict__ qh, const __half* __restrict__ kh,
    const __half* __restrict__ vth, const int* __restrict__ mask,
    const int* __restrict__ perm, float* __restrict__ pO,
    float* __restrict__ pM, float* __restrict__ pL) {
  extern __shared__ char sm[];
  const uint32_t sb = smem_u32(sm);
  const int tid = threadIdx.x;
  const int lane = tid & 31;
  const int w = tid >> 5;
  const int g = lane >> 2;
  const int c = lane & 3;

  const int bi = blockIdx.x;
  const int z = bi & 3;                 // batch fastest
  const int rest = bi >> 2;
  const int split = rest & 1;           // split next
  const int qt = 31 - (rest >> 1);      // longest qtiles first
  const int bm = qt * 128;

  const __half* qp = qh + (size_t)z * 4096 * 256;
  const __half* kp = kh + (size_t)z * 4096 * 256;
  const __half* vp = vth + (size_t)z * 256 * 4096;
  const int* permz = perm + z * 4096 + bm;
  const size_t pbase = (size_t)split * 16384 + (size_t)z * 4096;

  __shared__ int s_ctamax;
  if (tid == 0) s_ctamax = 0;
  __syncthreads();

  const int qiA = permz[w * 16 + g];
  const int qiB = permz[w * 16 + 8 + g];
  const int lenA = mask[z * 4096 + qiA];
  const int lenB = mask[z * 4096 + qiB];
  int wmax = max(lenA, lenB);
#pragma unroll
  for (int o = 4; o < 32; o <<= 1) wmax = max(wmax, __shfl_xor_sync(0xffffffffu, wmax, o));
  if (lane == 0) atomicMax(&s_ctamax, wmax);
  __syncthreads();

  const int t0 = split * (2048 / 64);
  const int tend = min((split + 1) * (2048 / 64), (s_ctamax + 63) >> 6);
  if (tend <= t0) {
    if (tid < 128) {
      const int qi = permz[tid];
      pM[pbase + qi] = -1e30f;
      pL[pbase + qi] = 0.0f;
    }
    return;
  }

  // Q tile (gathered)
#pragma unroll
  for (int i = 0; i < 16; i++) {
    const int idx = tid + i * 256;
    const int row = idx >> 5, ch = idx & 31;
    const int qrow = permz[row];
    cp16(sb + OFF_Q + row * 528 + ch * 16, qp + (size_t)qrow * 256 + ch * 8);
  }
  cp_commit();

  auto load_kv = [&](int stage, int kt) {
    const uint32_t ko = sb + (stage ? OFF_K1 : OFF_K0);
    const uint32_t vo = sb + (stage ? OFF_V1 : OFF_V0);
#pragma unroll
    for (int i = 0; i < 8; i++) {
      const int idx = tid + i * 256;
      const int row = idx >> 5, ch = idx & 31;
      cp16(ko + row * 528 + ch * 16, kp + (size_t)(kt * 64 + row) * 256 + ch * 8);
    }
#pragma unroll
    for (int i = 0; i < 8; i++) {
      const int idx = tid + i * 256;
      const int row = idx >> 3, ch = idx & 7;
      cp16(vo + row * 144 + ch * 16, vp + (size_t)row * 4096 + kt * 64 + ch * 8);
    }
    cp_commit();
  };

  load_kv(0, t0);

  float O[32][4];
#pragma unroll
  for (int i = 0; i < 32; i++)
#pragma unroll
    for (int j = 0; j < 4; j++) O[i][j] = 0.0f;
  float m0 = -1e30f, m1 = -1e30f, l0 = 0.0f, l1 = 0.0f;

  for (int kt = t0; kt < tend; kt++) {
    const int buf = kt & 1;
    if (kt + 1 < tend) {
      load_kv(buf ^ 1, kt + 1);
      cp_wait<1>();
    } else {
      cp_wait<0>();
    }
    __syncthreads();

    if (kt * 64 < wmax) {
      float S[8][4];
#pragma unroll
      for (int nt = 0; nt < 8; nt++)
#pragma unroll
        for (int j = 0; j < 4; j++) S[nt][j] = 0.0f;

      const uint32_t* Qs = (const uint32_t*)(sm + OFF_Q) + (w * 16 + g) * 132 + c;
      const uint32_t* Ks =
          (const uint32_t*)(sm + (buf ? OFF_K1 : OFF_K0)) + g * 132 + c;
#pragma unroll
      for (int ks = 0; ks < 16; ks++) {
        uint32_t a[4];
        a[0] = Qs[ks * 8];
        a[1] = Qs[ks * 8 + 8 * 132];
        a[2] = Qs[ks * 8 + 4];
        a[3] = Qs[ks * 8 + 8 * 132 + 4];
#pragma unroll
        for (int nt = 0; nt < 8; nt++) {
          uint32_t b[2];
          b[0] = Ks[nt * 8 * 132 + ks * 8];
          b[1] = Ks[nt * 8 * 132 + ks * 8 + 4];
          mma16(S[nt], a, b);
        }
      }

      const int kb = kt * 64;
      float tmax0 = -1e30f, tmax1 = -1e30f;
#pragma unroll
      for (int nt = 0; nt < 8; nt++) {
        const int col0 = kb + nt * 8 + c * 2;
        const int col1 = col0 + 1;
        float s00 = (col0 < lenA) ? S[nt][0] * 0.0625f : -1e30f;
        float s01 = (col1 < lenA) ? S[nt][1] * 0.0625f : -1e30f;
        float s10 = (col0 < lenB) ? S[nt][2] * 0.0625f : -1e30f;
        float s11 = (col1 < lenB) ? S[nt][3] * 0.0625f : -1e30f;
        S[nt][0] = s00; S[nt][1] = s01; S[nt][2] = s10; S[nt][3] = s11;
        tmax0 = fmaxf(tmax0, fmaxf(s00, s01));
        tmax1 = fmaxf(tmax1, fmaxf(s10, s11));
      }
      tmax0 = fmaxf(tmax0, __shfl_xor_sync(0xffffffffu, tmax0, 1));
      tmax0 = fmaxf(tmax0, __shfl_xor_sync(0xffffffffu, tmax0, 2));
      tmax1 = fmaxf(tmax1, __shfl_xor_sync(0xffffffffu, tmax1, 1));
      tmax1 = fmaxf(tmax1, __shfl_xor_sync(0xffffffffu, tmax1, 2));

      const float mn0 = fmaxf(m0, tmax0), mn1 = fmaxf(m1, tmax1);
      const float al0 = __expf(m0 - mn0), al1 = __expf(m1 - mn1);
      m0 = mn0; m1 = mn1;

      float sum0 = 0.0f, sum1 = 0.0f;
#pragma unroll
      for (int nt = 0; nt < 8; nt++) {
        S[nt][0] = __expf(S[nt][0] - mn0);
        S[nt][1] = __expf(S[nt][1] - mn0);
        S[nt][2] = __expf(S[nt][2] - mn1);
        S[nt][3] = __expf(S[nt][3] - mn1);
        sum0 += S[nt][0] + S[nt][1];
        sum1 += S[nt][2] + S[nt][3];
      }
      sum0 += __shfl_xor_sync(0xffffffffu, sum0, 1);
      sum0 += __shfl_xor_sync(0xffffffffu, sum0, 2);
      sum1 += __shfl_xor_sync(0xffffffffu, sum1, 1);
      sum1 += __shfl_xor_sync(0xffffffffu, sum1, 2);
      l0 = l0 * al0 + sum0;
      l1 = l1 * al1 + sum1;

#pragma unroll
      for (int nt2 = 0; nt2 < 32; nt2++) {
        O[nt2][0] *= al0; O[nt2][1] *= al0;
        O[nt2][2] *= al1; O[nt2][3] *= al1;
      }

      uint32_t pa[4][4];
#pragma unroll
      for (int ks2 = 0; ks2 < 4; ks2++) {
        pa[ks2][0] = pack_half2(S[2 * ks2][0], S[2 * ks2][1]);
        pa[ks2][1] = pack_half2(S[2 * ks2][2], S[2 * ks2][3]);
        pa[ks2][2] = pack_half2(S[2 * ks2 + 1][0], S[2 * ks2 + 1][1]);
        pa[ks2][3] = pack_half2(S[2 * ks2 + 1][2], S[2 * ks2 + 1][3]);
      }

      const uint32_t* Vs =
          (const uint32_t*)(sm + (buf ? OFF_V1 : OFF_V0)) + g * 36 + c;
#pragma unroll
      for (int ks2 = 0; ks2 < 4; ks2++) {
#pragma unroll
        for (int nt2 = 0; nt2 < 32; nt2++) {
          uint32_t b[2];
          b[0] = Vs[nt2 * 8 * 36 + ks2 * 8];
          b[1] = Vs[nt2 * 8 * 36 + ks2 * 8 + 4];
          mma16(O[nt2], pa[ks2], b);
        }
      }
    }
    __syncthreads();
  }

  float* opA = pO + (pbase + qiA) * 256;
  float* opB = pO + (pbase + qiB) * 256;
#pragma unroll
  for (int nt2 = 0; nt2 < 32; nt2++) {
    const int col = nt2 * 8 + c * 2;
    store2(opA + col, O[nt2][0], O[nt2][1]);
    store2(opB + col, O[nt2][2], O[nt2][3]);
  }
  if (c == 0) {
    pM[pbase + qiA] = m0; pL[pbase + qiA] = l0;
    pM[pbase + qiB] = m1; pL[pbase + qiB] = l1;
  }
}

// ---------------------------------------------------------------------------
// Combine: fast path when split-1 is sentinel (l1 == 0) skips its 64MB read.
// ---------------------------------------------------------------------------
__global__ __launch_bounds__(256) void combine_kernel(
    const float* __restrict__ pO, const float* __restrict__ pM,
    const float* __restrict__ pL, __half* __restrict__ atth) {
  const int row = blockIdx.x * 4 + (threadIdx.x >> 6);
  const int t = threadIdx.x & 63;
  const float l1 = pL[16384 + row];
  const float l0 = pL[row];
  const float4 a = ((const float4*)(pO + (size_t)row * 256))[t];
  float x0, x1, x2, x3;
  if (l1 == 0.0f) {
    const float inv = 1.0f / l0;
    x0 = a.x * inv; x1 = a.y * inv; x2 = a.z * inv; x3 = a.w * inv;
  } else {
    const float m0 = pM[row], m1 = pM[16384 + row];
    const float ms = fmaxf(m0, m1);
    const float w0 = __expf(m0 - ms), w1 = __expf(m1 - ms);
    const float inv = 1.0f / (l0 * w0 + l1 * w1);
    const float f0 = w0 * inv, f1 = w1 * inv;
    const float4 b = ((const float4*)(pO + ((size_t)(16384 + row)) * 256))[t];
    x0 = a.x * f0 + b.x * f1;
    x1 = a.y * f0 + b.y * f1;
    x2 = a.z * f0 + b.z * f1;
    x3 = a.w * f0 + b.w * f1;
  }
  ((__half2*)(atth + (size_t)row * 256))[2 * t] = __floats2half2_rn(x0, x1);
  ((__half2*)(atth + (size_t)row * 256))[2 * t + 1] = __floats2half2_rn(x2, x3);
}

// ---------------------------------------------------------------------------
// All 7 fp32 -> fp16 conversions in one launch (grid.y = job).
// ---------------------------------------------------------------------------
__global__ __launch_bounds__(256) void cvt_multi(
    const float* s0, __half* d0, int n0, const float* s1, __half* d1, int n1,
    const float* s2, __half* d2, int n2, const float* s3, __half* d3, int n3,
    const float* s4, __half* d4, int n4_, const float* s5, __half* d5, int n5,
    const float* s6, __half* d6, int n6) {
  const float* ss[7] = {s0, s1, s2, s3, s4, s5, s6};
  __half* dd[7] = {d0, d1, d2, d3, d4, d5, d6};
  const int nn[7] = {n0, n1, n2, n3, n4_, n5, n6};
  const int j = blockIdx.y;
  const int i = blockIdx.x * blockDim.x + threadIdx.x;
  if (i < nn[j]) {
    float4 f = ((const float4*)ss[j])[i];
    ((__half2*)dd[j])[2 * i] = __floats2half2_rn(f.x, f.y);
    ((__half2*)dd[j])[2 * i + 1] = __floats2half2_rn(f.z, f.w);
  }
}

// ---------------------------------------------------------------------------
// Batched transpose (half): vt[b][n][k] = v[b][k][n]
// ---------------------------------------------------------------------------
__global__ __launch_bounds__(256) void transpose_h(
    const __half* __restrict__ v, __half* __restrict__ vt) {
  __shared__ __half t[32][33];
  const int b = blockIdx.z;
  const int k0 = blockIdx.x * 32;
  const int n0 = blockIdx.y * 32;
  const int tx = threadIdx.x & 31;
  const int ty = threadIdx.x >> 5;
  const __half* src = v + (size_t)b * 4096 * 256;
  __half* dst = vt + (size_t)b * 256 * 4096;
#pragma unroll
  for (int i = 0; i < 32; i += 8)
    t[ty + i][tx] = src[(size_t)(k0 + ty + i) * 256 + n0 + tx];
  __syncthreads();
#pragma unroll
  for (int i = 0; i < 32; i += 8)
    dst[(size_t)(n0 + ty + i) * 4096 + k0 + tx] = t[tx][ty + i];
}

// ---------------------------------------------------------------------------
// Launch
// ---------------------------------------------------------------------------
extern "C" void kernel_launch(void* const* d_in, const int* in_sizes, int n_in,
                              void* d_out, int out_size) {
  const float* queries = (const float*)d_in[0];
  const float* keys    = (const float*)d_in[1];
  const float* values  = (const float*)d_in[2];
  const int*   mask    = (const int*)d_in[3];
  const float* Wq = (const float*)d_in[4];
  const float* bq = (const float*)d_in[5];
  const float* Wk = (const float*)d_in[6];
  const float* bk = (const float*)d_in[7];
  const float* Wv = (const float*)d_in[8];
  const float* bv = (const float*)d_in[9];
  const float* Wo = (const float*)d_in[10];
  const float* bo = (const float*)d_in[11];
  float* out = (float*)d_out;

  __half *xq, *xk, *xv, *wq, *wk, *wv, *wo;
  __half *qh, *kh, *vh, *vth, *atth;
  int *startp, *permp;
  float *pO, *pM, *pL;
  cudaGetSymbolAddress((void**)&xq, g_xq);
  cudaGetSymbolAddress((void**)&xk, g_xk);
  cudaGetSymbolAddress((void**)&xv, g_xv);
  cudaGetSymbolAddress((void**)&wq, g_wq);
  cudaGetSymbolAddress((void**)&wk, g_wk);
  cudaGetSymbolAddress((void**)&wv, g_wv);
  cudaGetSymbolAddress((void**)&wo, g_wo);
  cudaGetSymbolAddress((void**)&qh, g_qh);
  cudaGetSymbolAddress((void**)&kh, g_kh);
  cudaGetSymbolAddress((void**)&vh, g_vh);
  cudaGetSymbolAddress((void**)&vth, g_vth);
  cudaGetSymbolAddress((void**)&atth, g_atth);
  cudaGetSymbolAddress((void**)&startp, g_start);
  cudaGetSymbolAddress((void**)&permp, g_perm);
  cudaGetSymbolAddress((void**)&pO, g_pO);
  cudaGetSymbolAddress((void**)&pM, g_pM);
  cudaGetSymbolAddress((void**)&pL, g_pL);

  cudaFuncSetAttribute(hgemm_qkv,
                       cudaFuncAttributeMaxDynamicSharedMemorySize, GEMM_SMEM);
  cudaFuncSetAttribute(hgemm_out,
                       cudaFuncAttributeMaxDynamicSharedMemorySize, GEMM_SMEM);
  cudaFuncSetAttribute(flash_attn,
                       cudaFuncAttributeMaxDynamicSharedMemorySize, FLASH_SMEM);

  dim3 blk(256);

  // query-length sort
  sort_hist_scan<<<4, 1024>>>(mask, startp);
  sort_scatter<<<dim3(16, 4), blk>>>(mask, startp, permp);

  // fp32 -> fp16, one launch
  const int NTOK4 = 4 * 4096 * 256 / 4;
  const int NW4 = 65536 / 4;
  cvt_multi<<<dim3(NTOK4 / 256, 7), blk>>>(
      queries, xq, NTOK4, keys, xk, NTOK4, values, xv, NTOK4,
      Wq, wq, NW4, Wk, wk, NW4, Wv, wv, NW4, Wo, wo, NW4);

  // Fused QKV projections
  hgemm_qkv<<<dim3(2, 128, 3), blk, GEMM_SMEM>>>(
      xq, wq, bq, qh, xk, wk, bk, kh, xv, wv, bv, vh);

  // vT for flash V tiles
  transpose_h<<<dim3(128, 8, 4), blk>>>(vh, vth);

  // Split-KV fused attention (1D wave-aware grid)
  flash_attn<<<dim3(32 * 4 * SPLIT, 1, 1), blk, FLASH_SMEM>>>(
      qh, kh, vth, mask, permp, pO, pM, pL);

  // Combine partials -> atth
  combine_kernel<<<4096, blk>>>(pO, pM, pL, atth);

  // Output projection -> fp32
  hgemm_out<<<dim3(2, 128, 1), blk, GEMM_SMEM>>>(atth, wo, bo, out);
}